// round 4
// baseline (speedup 1.0000x reference)
#include <cuda_runtime.h>

// ---------------------------------------------------------------------------
// DctLayer: per 8x8 block, out0 = L*B*L^T, out1 = L*B - out0, out2 = H*B*L^T,
// out3 = H*B - out2, with L = rank-4 DCT low-pass projector, H = I - L.
// Pure HBM-streaming problem (~503 MB). 8 threads per block (one per row),
// vertical mix via warp shuffles -> ~65 regs/thread, 4x occupancy vs R2.
//
// L has DCT even/odd symmetry: L*a = butterfly + two 4x4 matvecs (E, O):
//   E[i][x] = 0.125 + 0.25*g[i]*g[x],          g  = [c2, c6, -c6, -c2]
//   O[i][x] = 0.25*(h1[i]h1[x] + h3[i]h3[x]),  h1 = [c1,c3,c5,c7], h3 = [c3,-c7,-c1,-c5]
// (cm = cos(m*pi/16)). Verified: trace(L) = 4, L*1 = 1, rel_err 7.6e-7 in R2.
// R4 fix: vertical h = e + o (no 0.5 factor — lane butterfly already matches
// lmix8's unnormalized S/D convention; checked against L*1 = 1).
// ---------------------------------------------------------------------------

#define E00 0.33838834764831845f
#define E01 0.21338834764831843f
#define E02 0.03661165235168157f
#define E03 (-0.08838834764831845f)
#define E11 0.16161165235168156f
#define E12 0.08838834764831844f
#define E13 0.03661165235168157f
#define E22 0.16161165235168156f
#define E23 0.21338834764831843f
#define E33 0.33838834764831845f

#define O00 0.41332037060954707f
#define O01 0.16332037060954707f
#define O02 (-0.06764951251827464f)
#define O03 (-0.06764951251827464f)
#define O11 0.18235048748172537f
#define O12 0.16332037060954707f
#define O13 0.06764951251827464f
#define O22 0.31764951251827466f
#define O23 0.16332037060954707f
#define O33 0.08667962939045293f

__device__ __constant__ float cEmat[4][4] = {
    { E00, E01, E02, E03 },
    { E01, E11, E12, E13 },
    { E02, E12, E22, E23 },
    { E03, E13, E23, E33 } };
__device__ __constant__ float cOmat[4][4] = {
    { O00, O01, O02, O03 },
    { O01, O11, O12, O13 },
    { O02, O12, O22, O23 },
    { O03, O13, O23, O33 } };

// Horizontal (within-row) r = L * a: butterfly + two 4x4 matvecs with
// compile-time literal coefficients -> FFMA-imm form (rt_SMSP = 1).
__device__ __forceinline__ void lmix8(const float a[8], float r[8]) {
    float s0 = a[0] + a[7], s1 = a[1] + a[6], s2 = a[2] + a[5], s3 = a[3] + a[4];
    float d0 = a[0] - a[7], d1 = a[1] - a[6], d2 = a[2] - a[5], d3 = a[3] - a[4];

    float e0 = E00 * s0 + E01 * s1 + E02 * s2 + E03 * s3;
    float e1 = E01 * s0 + E11 * s1 + E12 * s2 + E13 * s3;
    float e2 = E02 * s0 + E12 * s1 + E22 * s2 + E23 * s3;
    float e3 = E03 * s0 + E13 * s1 + E23 * s2 + E33 * s3;

    float o0 = O00 * d0 + O01 * d1 + O02 * d2 + O03 * d3;
    float o1 = O01 * d0 + O11 * d1 + O12 * d2 + O13 * d3;
    float o2 = O02 * d0 + O12 * d1 + O22 * d2 + O23 * d3;
    float o3 = O03 * d0 + O13 * d1 + O23 * d2 + O33 * d3;

    r[0] = e0 + o0;  r[7] = e0 - o0;
    r[1] = e1 + o1;  r[6] = e1 - o1;
    r[2] = e2 + o2;  r[5] = e2 - o2;
    r[3] = e3 + o3;  r[4] = e3 - o3;
}

// 8 threads per 8x8 block, one image row per thread.
// 96 ch * 64 * 64 blocks * 8 rows = 3,145,728 threads = 12288 CTAs of 256.
__global__ void __launch_bounds__(256, 4)
dct_corner_kernel(const float* __restrict__ x, float* __restrict__ out)
{
    int t  = blockIdx.x * 256 + threadIdx.x;
    int r  = t & 7;            // row within block (== lane & 7)
    int p  = t >> 3;           // block index
    int bx = p & 63;
    int by = (p >> 6) & 63;
    int ch = p >> 12;

    const float* src = x + ((size_t)ch << 18) + (size_t)(by * 8 + r) * 512 + (bx << 3);

    // Load my row: lanes r, r+8, r+16, r+24 cover 4 adjacent blocks ->
    // contiguous 128B lines, fully consumed.
    float v[8];
    {
        float4 v0 = __ldg((const float4*)src);
        float4 v1 = __ldg((const float4*)(src + 4));
        v[0] = v0.x; v[1] = v0.y; v[2] = v0.z; v[3] = v0.w;
        v[4] = v1.x; v[5] = v1.y; v[6] = v1.z; v[7] = v1.w;
    }

    // Per-lane vertical-mix coefficients: rr = min(r, 7-r);
    // cE[m] = E[rr][rr^m], cO[m] = O[rr][rr^m]. Sign of d cancels:
    // upper-half lanes hold (S, -D) and their mask-1/2/3 neighbors stay in
    // the upper half, so o = -sum(O*D) and e + o is the correct row anyway.
    int rr = (r < 4) ? r : (7 - r);
    float cE0 = cEmat[rr][rr ^ 0], cE1 = cEmat[rr][rr ^ 1];
    float cE2 = cEmat[rr][rr ^ 2], cE3 = cEmat[rr][rr ^ 3];
    float cO0 = cOmat[rr][rr ^ 0], cO1 = cOmat[rr][rr ^ 1];
    float cO2 = cOmat[rr][rr ^ 2], cO3 = cOmat[rr][rr ^ 3];

    // Vertical stage across lanes: r0 = (L*B) row r, r1 = B - r0.
    float r0[8], r1[8];
#pragma unroll
    for (int j = 0; j < 8; ++j) {
        float w = __shfl_xor_sync(0xffffffffu, v[j], 7);
        float s = v[j] + w;
        float d = v[j] - w;
        float s1 = __shfl_xor_sync(0xffffffffu, s, 1);
        float s2 = __shfl_xor_sync(0xffffffffu, s, 2);
        float s3 = __shfl_xor_sync(0xffffffffu, s, 3);
        float d1 = __shfl_xor_sync(0xffffffffu, d, 1);
        float d2 = __shfl_xor_sync(0xffffffffu, d, 2);
        float d3 = __shfl_xor_sync(0xffffffffu, d, 3);
        float e = cE0 * s + cE1 * s1 + cE2 * s2 + cE3 * s3;
        float o = cO0 * d + cO1 * d1 + cO2 * d2 + cO3 * d3;
        float h = e + o;
        r0[j] = h;
        r1[j] = v[j] - h;
    }

    // Horizontal stage on my two rows + streamed stores to the 4 planes.
    const size_t PL = (size_t)96 * 512 * 512;
    float* pO = out + ((size_t)ch << 18) + (size_t)(by * 8 + r) * 512 + (bx << 3);

    float tq[8], u[8];

    lmix8(r0, tq);                                   // out0 row
#pragma unroll
    for (int j = 0; j < 8; ++j) u[j] = r0[j] - tq[j]; // out1 row
    *(float4*)(pO)          = make_float4(tq[0], tq[1], tq[2], tq[3]);
    *(float4*)(pO + 4)      = make_float4(tq[4], tq[5], tq[6], tq[7]);
    *(float4*)(pO + PL)     = make_float4(u[0], u[1], u[2], u[3]);
    *(float4*)(pO + PL + 4) = make_float4(u[4], u[5], u[6], u[7]);

    lmix8(r1, tq);                                   // out2 row
#pragma unroll
    for (int j = 0; j < 8; ++j) u[j] = r1[j] - tq[j]; // out3 row
    *(float4*)(pO + 2 * PL)     = make_float4(tq[0], tq[1], tq[2], tq[3]);
    *(float4*)(pO + 2 * PL + 4) = make_float4(tq[4], tq[5], tq[6], tq[7]);
    *(float4*)(pO + 3 * PL)     = make_float4(u[0], u[1], u[2], u[3]);
    *(float4*)(pO + 3 * PL + 4) = make_float4(u[4], u[5], u[6], u[7]);
}

extern "C" void kernel_launch(void* const* d_in, const int* in_sizes, int n_in,
                              void* d_out, int out_size) {
    const float* x = (const float*)d_in[0];
    float* out     = (float*)d_out;

    // 8 threads per 8x8 block
    int total_threads = (in_sizes[0] / 64) * 8;     // 3,145,728
    int grid = total_threads / 256;                 // 12288
    dct_corner_kernel<<<grid, 256>>>(x, out);
}

// round 5
// speedup vs baseline: 1.7146x; 1.7146x over previous
#include <cuda_runtime.h>

// ---------------------------------------------------------------------------
// DctLayer: per 8x8 block, out0 = L*B*L^T, out1 = L*B - out0, out2 = H*B*L^T,
// out3 = H*B - out2, with L = rank-4 DCT low-pass projector, H = I - L.
// Pure HBM-streaming problem (~503 MB).
//
// R5 design: 2 threads per block. Even lane owns cols 0-3; odd lane owns
// cols 4-7 with REVERSED slot convention (slot j = col 7-j). This gives:
//   - fully contiguous 512B LDG.128/STG.128 per warp (4 wavefronts, not 8)
//   - vertical mix shuffle-free (thread holds all 8 rows of its columns)
//   - horizontal mix with 4 shfl_xor(,1) per row; slot reversal makes the
//     butterfly sums canonical in both parities and the odd lane's sign on d
//     cancels against its needing e-o instead of e+o -> one uniform
//     immediate-constant formula, no divergence.
//
// L*a = butterfly + two 4x4 matvecs (E, O):
//   E[i][x] = 0.125 + 0.25*g[i]*g[x],          g  = [c2, c6, -c6, -c2]
//   O[i][x] = 0.25*(h1[i]h1[x] + h3[i]h3[x]),  h1 = [c1,c3,c5,c7], h3 = [c3,-c7,-c1,-c5]
// Constants validated in R2/R4 (rel_err 7.6e-7).
// ---------------------------------------------------------------------------

#define E00 0.33838834764831845f
#define E01 0.21338834764831843f
#define E02 0.03661165235168157f
#define E03 (-0.08838834764831845f)
#define E11 0.16161165235168156f
#define E12 0.08838834764831844f
#define E13 0.03661165235168157f
#define E22 0.16161165235168156f
#define E23 0.21338834764831843f
#define E33 0.33838834764831845f

#define O00 0.41332037060954707f
#define O01 0.16332037060954707f
#define O02 (-0.06764951251827464f)
#define O03 (-0.06764951251827464f)
#define O11 0.18235048748172537f
#define O12 0.16332037060954707f
#define O13 0.06764951251827464f
#define O22 0.31764951251827466f
#define O23 0.16332037060954707f
#define O33 0.08667962939045293f

// Full 8-vector r = L * a (vertical stage; all-immediate FFMA).
__device__ __forceinline__ void lmix8(const float a[8], float r[8]) {
    float s0 = a[0] + a[7], s1 = a[1] + a[6], s2 = a[2] + a[5], s3 = a[3] + a[4];
    float d0 = a[0] - a[7], d1 = a[1] - a[6], d2 = a[2] - a[5], d3 = a[3] - a[4];

    float e0 = E00 * s0 + E01 * s1 + E02 * s2 + E03 * s3;
    float e1 = E01 * s0 + E11 * s1 + E12 * s2 + E13 * s3;
    float e2 = E02 * s0 + E12 * s1 + E22 * s2 + E23 * s3;
    float e3 = E03 * s0 + E13 * s1 + E23 * s2 + E33 * s3;

    float o0 = O00 * d0 + O01 * d1 + O02 * d2 + O03 * d3;
    float o1 = O01 * d0 + O11 * d1 + O12 * d2 + O13 * d3;
    float o2 = O02 * d0 + O12 * d1 + O22 * d2 + O23 * d3;
    float o3 = O03 * d0 + O13 * d1 + O23 * d2 + O33 * d3;

    r[0] = e0 + o0;  r[7] = e0 - o0;
    r[1] = e1 + o1;  r[6] = e1 - o1;
    r[2] = e2 + o2;  r[5] = e2 - o2;
    r[3] = e3 + o3;  r[4] = e3 - o3;
}

// Horizontal half-row mix. m0..m3 = this lane's 4 slots of one row.
// recv_j (lane-pair exchange) is exactly the butterfly partner of slot j in
// both parities; d carries a per-parity sign that cancels against e+/-o.
__device__ __forceinline__ void hmix4(float m0, float m1, float m2, float m3,
                                      float& t0, float& t1, float& t2, float& t3) {
    float r0 = __shfl_xor_sync(0xffffffffu, m0, 1);
    float r1 = __shfl_xor_sync(0xffffffffu, m1, 1);
    float r2 = __shfl_xor_sync(0xffffffffu, m2, 1);
    float r3 = __shfl_xor_sync(0xffffffffu, m3, 1);

    float s0 = m0 + r0, s1 = m1 + r1, s2 = m2 + r2, s3 = m3 + r3;
    float d0 = m0 - r0, d1 = m1 - r1, d2 = m2 - r2, d3 = m3 - r3;

    t0 = E00*s0 + E01*s1 + E02*s2 + E03*s3 + O00*d0 + O01*d1 + O02*d2 + O03*d3;
    t1 = E01*s0 + E11*s1 + E12*s2 + E13*s3 + O01*d0 + O11*d1 + O12*d2 + O13*d3;
    t2 = E02*s0 + E12*s1 + E22*s2 + E23*s3 + O02*d0 + O12*d1 + O22*d2 + O23*d3;
    t3 = E03*s0 + E13*s1 + E23*s2 + E33*s3 + O03*d0 + O13*d1 + O23*d2 + O33*d3;
}

// Marshal 4 slots into a store float4; odd lanes un-reverse (slot j = col 7-j).
__device__ __forceinline__ float4 marsh(int half, float a0, float a1, float a2, float a3) {
    return half ? make_float4(a3, a2, a1, a0) : make_float4(a0, a1, a2, a3);
}

// 2 threads per 8x8 block. 393216 blocks -> 786432 threads -> 3072 CTAs.
__global__ void __launch_bounds__(256, 2)
dct_corner_kernel(const float* __restrict__ x, float* __restrict__ out)
{
    int t    = blockIdx.x * 256 + threadIdx.x;
    int half = t & 1;                 // 0: cols 0-3, 1: cols 4-7 (reversed slots)
    int p    = t >> 1;                // block index
    int bx   = p & 63;
    int by   = (p >> 6) & 63;
    int ch   = p >> 12;

    const float* src = x + ((size_t)ch << 18) + (size_t)(by << 3) * 512
                         + (bx << 3) + (half << 2);

    // Load my half of all 8 rows. Lane pairs are 16B-contiguous ->
    // each LDG.128 covers a full 512B span (4 wavefronts).
    float v[8][4];
#pragma unroll
    for (int r = 0; r < 8; ++r) {
        float4 q = __ldcs((const float4*)(src + (size_t)r * 512));
        v[r][0] = half ? q.w : q.x;
        v[r][1] = half ? q.z : q.y;
        v[r][2] = half ? q.y : q.z;
        v[r][3] = half ? q.x : q.w;
    }

    // Vertical stage per local column (shuffle-free): lo = L*B cols, v -> hi.
    float lo[8][4];
#pragma unroll
    for (int c = 0; c < 4; ++c) {
        float a[8], rr[8];
#pragma unroll
        for (int r = 0; r < 8; ++r) a[r] = v[r][c];
        lmix8(a, rr);
#pragma unroll
        for (int r = 0; r < 8; ++r) { lo[r][c] = rr[r]; v[r][c] -= rr[r]; }
    }

    // Horizontal stage + streamed stores to the 4 output planes.
    const size_t PL = (size_t)96 * 512 * 512;
    float* pO = out + ((size_t)ch << 18) + (size_t)(by << 3) * 512
                    + (bx << 3) + (half << 2);

#pragma unroll
    for (int r = 0; r < 8; ++r) {
        float* pr = pO + (size_t)r * 512;
        float t0, t1, t2, t3;

        // low-pass rows -> out0 (= L*B*L^T) and out1 (= L*B - out0)
        hmix4(lo[r][0], lo[r][1], lo[r][2], lo[r][3], t0, t1, t2, t3);
        __stcs((float4*)(pr),      marsh(half, t0, t1, t2, t3));
        __stcs((float4*)(pr + PL), marsh(half, lo[r][0] - t0, lo[r][1] - t1,
                                               lo[r][2] - t2, lo[r][3] - t3));

        // high-pass rows -> out2 (= H*B*L^T) and out3 (= H*B - out2)
        hmix4(v[r][0], v[r][1], v[r][2], v[r][3], t0, t1, t2, t3);
        __stcs((float4*)(pr + 2 * PL), marsh(half, t0, t1, t2, t3));
        __stcs((float4*)(pr + 3 * PL), marsh(half, v[r][0] - t0, v[r][1] - t1,
                                                   v[r][2] - t2, v[r][3] - t3));
    }
}

extern "C" void kernel_launch(void* const* d_in, const int* in_sizes, int n_in,
                              void* d_out, int out_size) {
    const float* x = (const float*)d_in[0];
    float* out     = (float*)d_out;

    // 2 threads per 8x8 block
    int total_threads = (in_sizes[0] / 64) * 2;     // 786432
    int grid = total_threads / 256;                 // 3072
    dct_corner_kernel<<<grid, 256>>>(x, out);
}

// round 6
// speedup vs baseline: 1.7546x; 1.0233x over previous
#include <cuda_runtime.h>

// ---------------------------------------------------------------------------
// DctLayer: per 8x8 block, out0 = L*B*L^T, out1 = L*B - out0, out2 = H*B*L^T,
// out3 = H*B - out2, with L = rank-4 DCT low-pass projector, H = I - L.
// Pure HBM-streaming problem (~503 MB).
//
// R6: same memory layout as R5 (2 threads/block, even lane cols 0-3, odd lane
// cols 4-7 slot-reversed; all LDG/STG.128 fully contiguous per warp), but the
// vertical stage is kept in butterfly (s,d) space: s[4][4]+d[4][4] = 32 live
// floats instead of v+lo = 64. Each row-pair (rr, 7-rr) is materialized,
// stored, and freed. Peak regs ~75 -> 3 CTAs/SM (launch_bounds(256,3)) for
// ~1.5x occupancy vs R5 to raise DRAM duty cycle.
//
// L*a = butterfly + two 4x4 matvecs (E, O):
//   E[i][x] = 0.125 + 0.25*g[i]*g[x],          g  = [c2, c6, -c6, -c2]
//   O[i][x] = 0.25*(h1[i]h1[x] + h3[i]h3[x]),  h1 = [c1,c3,c5,c7], h3 = [c3,-c7,-c1,-c5]
// Constants validated in R2/R4/R5 (rel_err 7.6e-7).
// ---------------------------------------------------------------------------

#define E00 0.33838834764831845f
#define E01 0.21338834764831843f
#define E02 0.03661165235168157f
#define E03 (-0.08838834764831845f)
#define E11 0.16161165235168156f
#define E12 0.08838834764831844f
#define E13 0.03661165235168157f
#define E22 0.16161165235168156f
#define E23 0.21338834764831843f
#define E33 0.33838834764831845f

#define O00 0.41332037060954707f
#define O01 0.16332037060954707f
#define O02 (-0.06764951251827464f)
#define O03 (-0.06764951251827464f)
#define O11 0.18235048748172537f
#define O12 0.16332037060954707f
#define O13 0.06764951251827464f
#define O22 0.31764951251827466f
#define O23 0.16332037060954707f
#define O33 0.08667962939045293f

// constexpr tables: indexed only with compile-time indices -> folded to
// immediates by nvcc (FFMA-imm form).
__device__ constexpr float Ec[4][4] = {
    { E00, E01, E02, E03 },
    { E01, E11, E12, E13 },
    { E02, E12, E22, E23 },
    { E03, E13, E23, E33 } };
__device__ constexpr float Oc[4][4] = {
    { O00, O01, O02, O03 },
    { O01, O11, O12, O13 },
    { O02, O12, O22, O23 },
    { O03, O13, O23, O33 } };

// Horizontal half-row mix (same as R5): lane-pair exchange is the butterfly
// partner in both parities; the parity sign on d cancels against e +/- o.
__device__ __forceinline__ void hmix4(float m0, float m1, float m2, float m3,
                                      float& t0, float& t1, float& t2, float& t3) {
    float r0 = __shfl_xor_sync(0xffffffffu, m0, 1);
    float r1 = __shfl_xor_sync(0xffffffffu, m1, 1);
    float r2 = __shfl_xor_sync(0xffffffffu, m2, 1);
    float r3 = __shfl_xor_sync(0xffffffffu, m3, 1);

    float s0 = m0 + r0, s1 = m1 + r1, s2 = m2 + r2, s3 = m3 + r3;
    float d0 = m0 - r0, d1 = m1 - r1, d2 = m2 - r2, d3 = m3 - r3;

    t0 = E00*s0 + E01*s1 + E02*s2 + E03*s3 + O00*d0 + O01*d1 + O02*d2 + O03*d3;
    t1 = E01*s0 + E11*s1 + E12*s2 + E13*s3 + O01*d0 + O11*d1 + O12*d2 + O13*d3;
    t2 = E02*s0 + E12*s1 + E22*s2 + E23*s3 + O02*d0 + O12*d1 + O22*d2 + O23*d3;
    t3 = E03*s0 + E13*s1 + E23*s2 + E33*s3 + O03*d0 + O13*d1 + O23*d2 + O33*d3;
}

__device__ __forceinline__ float4 marsh(int half, float a0, float a1, float a2, float a3) {
    return half ? make_float4(a3, a2, a1, a0) : make_float4(a0, a1, a2, a3);
}

// Produce one vertical row-pair (rows RR and 7-RR) from s/d space.
template <int RR>
__device__ __forceinline__ void vpair(const float s[4][4], const float d[4][4],
                                      float loT[4], float loB[4],
                                      float hiT[4], float hiB[4]) {
#pragma unroll
    for (int c = 0; c < 4; ++c) {
        float e = Ec[RR][0]*s[0][c] + Ec[RR][1]*s[1][c]
                + Ec[RR][2]*s[2][c] + Ec[RR][3]*s[3][c];
        float o = Oc[RR][0]*d[0][c] + Oc[RR][1]*d[1][c]
                + Oc[RR][2]*d[2][c] + Oc[RR][3]*d[3][c];
        loT[c] = e + o;                                   // lo row RR
        loB[c] = e - o;                                   // lo row 7-RR
        hiT[c] = 0.5f*s[RR][c] + 0.5f*d[RR][c] - loT[c];  // v_RR   - lo_RR
        hiB[c] = 0.5f*s[RR][c] - 0.5f*d[RR][c] - loB[c];  // v_7-RR - lo_7-RR
    }
}

// 2 threads per 8x8 block. 393216 blocks -> 786432 threads -> 3072 CTAs.
__global__ void __launch_bounds__(256, 3)
dct_corner_kernel(const float* __restrict__ x, float* __restrict__ out)
{
    int t    = blockIdx.x * 256 + threadIdx.x;
    int half = t & 1;                 // 0: cols 0-3, 1: cols 4-7 (reversed slots)
    int p    = t >> 1;                // block index
    int bx   = p & 63;
    int by   = (p >> 6) & 63;
    int ch   = p >> 12;

    const float* src = x + ((size_t)ch << 18) + (size_t)(by << 3) * 512
                         + (bx << 3) + (half << 2);

    // Front-batched loads of all 8 rows (MLP), 512B-contiguous per warp.
    float4 q[8];
#pragma unroll
    for (int r = 0; r < 8; ++r)
        q[r] = __ldcs((const float4*)(src + (size_t)r * 512));

    // Fold into vertical butterfly space: s/d per row-pair. q freed here.
    float s[4][4], d[4][4];
#pragma unroll
    for (int rr = 0; rr < 4; ++rr) {
        float at[4], ab[4];
        at[0] = half ? q[rr].w : q[rr].x;  at[1] = half ? q[rr].z : q[rr].y;
        at[2] = half ? q[rr].y : q[rr].z;  at[3] = half ? q[rr].x : q[rr].w;
        int rb = 7 - rr;
        ab[0] = half ? q[rb].w : q[rb].x;  ab[1] = half ? q[rb].z : q[rb].y;
        ab[2] = half ? q[rb].y : q[rb].z;  ab[3] = half ? q[rb].x : q[rb].w;
#pragma unroll
        for (int c = 0; c < 4; ++c) { s[rr][c] = at[c] + ab[c]; d[rr][c] = at[c] - ab[c]; }
    }

    const size_t PL = (size_t)96 * 512 * 512;
    float* pO = out + ((size_t)ch << 18) + (size_t)(by << 3) * 512
                    + (bx << 3) + (half << 2);

#define DO_PAIR(RR)                                                            \
    {                                                                          \
        float loT[4], loB[4], hiT[4], hiB[4];                                  \
        vpair<RR>(s, d, loT, loB, hiT, hiB);                                   \
        float* pT = pO + (size_t)(RR) * 512;                                   \
        float* pB = pO + (size_t)(7 - (RR)) * 512;                             \
        float t0, t1, t2, t3;                                                  \
        hmix4(loT[0], loT[1], loT[2], loT[3], t0, t1, t2, t3);                 \
        __stcs((float4*)(pT),      marsh(half, t0, t1, t2, t3));               \
        __stcs((float4*)(pT + PL), marsh(half, loT[0]-t0, loT[1]-t1,           \
                                               loT[2]-t2, loT[3]-t3));         \
        hmix4(hiT[0], hiT[1], hiT[2], hiT[3], t0, t1, t2, t3);                 \
        __stcs((float4*)(pT + 2*PL), marsh(half, t0, t1, t2, t3));             \
        __stcs((float4*)(pT + 3*PL), marsh(half, hiT[0]-t0, hiT[1]-t1,         \
                                                 hiT[2]-t2, hiT[3]-t3));       \
        hmix4(loB[0], loB[1], loB[2], loB[3], t0, t1, t2, t3);                 \
        __stcs((float4*)(pB),      marsh(half, t0, t1, t2, t3));               \
        __stcs((float4*)(pB + PL), marsh(half, loB[0]-t0, loB[1]-t1,           \
                                               loB[2]-t2, loB[3]-t3));         \
        hmix4(hiB[0], hiB[1], hiB[2], hiB[3], t0, t1, t2, t3);                 \
        __stcs((float4*)(pB + 2*PL), marsh(half, t0, t1, t2, t3));             \
        __stcs((float4*)(pB + 3*PL), marsh(half, hiB[0]-t0, hiB[1]-t1,         \
                                                 hiB[2]-t2, hiB[3]-t3));       \
    }

    DO_PAIR(0)
    DO_PAIR(1)
    DO_PAIR(2)
    DO_PAIR(3)
#undef DO_PAIR
}

extern "C" void kernel_launch(void* const* d_in, const int* in_sizes, int n_in,
                              void* d_out, int out_size) {
    const float* x = (const float*)d_in[0];
    float* out     = (float*)d_out;

    // 2 threads per 8x8 block
    int total_threads = (in_sizes[0] / 64) * 2;     // 786432
    int grid = total_threads / 256;                 // 3072
    dct_corner_kernel<<<grid, 256>>>(x, out);
}